// round 4
// baseline (speedup 1.0000x reference)
#include <cuda_runtime.h>
#include <cuda_fp16.h>
#include <cuda.h>
#include <dlfcn.h>
#include <stdint.h>

// MultiLevelSparseHashEncoding — round 4.
// vs round 3 (121.5us, L1 80%, issue 52.7%): scatter output stores (32
// wavefronts/warp, ~57K cyc/SM of L1 time) replaced by coalesced SMEM
// staging + TMA 3D bulk store (box (4,1,256) over out[NPTS][8][4f]),
// double-buffered.  Tensormap encoded host-side via dlopen'd driver API;
// STG fallback if unavailable.

#define NLVL 16
#define NENC 16384
#define NPTS (1 << 20)
#define TPB  1024
#define PPB  8192
#define GPT  (PPB / TPB)            // 8 points per thread
#define NPAIR 8
#define STAGE_BYTES (2 * TPB * 16)                       // 32 KB double buffer
#define TAB_BYTES   ((2 * (NENC + 1)) * (int)sizeof(__half2))
#define SMEM_BYTES  (STAGE_BYTES + TAB_BYTES)            // 163848
#define SCALE    4096.0f
#define INV_SCALE (1.0f / 4096.0f)

__constant__ int c_res[NLVL] = {16, 20, 25, 32, 40, 50, 64, 80,
                                101, 128, 161, 203, 256, 322, 406, 512};
__constant__ int c_nle[NLVL] = {4096, 8000, 15625, 16384, 16384, 16384,
                                16384, 16384, 16384, 16384, 16384, 16384,
                                16384, 16384, 16384, 16384};

__device__ float g_xs[3u * NPTS];   // SoA coords scratch (12 MB)

// ---------------------------------------------------------------- pre-kernel
__global__ __launch_bounds__(1024)
void transpose_x_kernel(const float* __restrict__ x)
{
    const int p = blockIdx.x * 1024 + threadIdx.x;
    const float a = x[3 * p + 0];
    const float b = x[3 * p + 1];
    const float c = x[3 * p + 2];
    g_xs[p]             = a;
    g_xs[NPTS + p]      = b;
    g_xs[2u * NPTS + p] = c;
}

// ---------------------------------------------------------------- per-level
template <bool DIRECT>
__device__ __forceinline__ float2
level_feat(const __half2* __restrict__ tab, const int R,
           const float xv0, const float xv1, const float xv2)
{
    const float halfR = 0.5f * (float)R;
    const float t0 = __fadd_rn(__fmul_rn(__fadd_rn(xv0, 1.0f), halfR), -0.5f);
    const float t1 = __fadd_rn(__fmul_rn(__fadd_rn(xv1, 1.0f), halfR), -0.5f);
    const float t2 = __fadd_rn(__fmul_rn(__fadd_rn(xv2, 1.0f), halfR), -0.5f);

    const float fl0 = floorf(t0), fl1 = floorf(t1), fl2 = floorf(t2);
    const float fr0 = t0 - fl0, fr1 = t1 - fl1, fr2 = t2 - fl2;
    const int   i0  = (int)fl0, i1 = (int)fl1, i2 = (int)fl2;

    const float wx0 = i0     >= 0 ? 1.0f - fr0 : 0.0f;
    const float wx1 = i0 + 1 <  R ? fr0        : 0.0f;
    const float wy0 = i1     >= 0 ? 1.0f - fr1 : 0.0f;
    const float wy1 = i1 + 1 <  R ? fr1        : 0.0f;
    const float wz[2] = {i2     >= 0 ? 1.0f - fr2 : 0.0f,
                         i2 + 1 <  R ? fr2        : 0.0f};
    const float wxy[4] = {wx0 * wy0, wx0 * wy1, wx1 * wy0, wx1 * wy1};

    unsigned kx[2], ky[2], kz[2];
    if (DIRECT) {
        const int R2 = R * R;
        const int a0 = max(i0, 0), a1 = min(i0 + 1, R - 1);
        const int b0 = max(i1, 0), b1 = min(i1 + 1, R - 1);
        const int d0 = max(i2, 0), d1 = min(i2 + 1, R - 1);
        kx[0] = (unsigned)(a0 * R2); kx[1] = (unsigned)(a1 * R2);
        ky[0] = (unsigned)(b0 * R);  ky[1] = (unsigned)(b1 * R);
        kz[0] = (unsigned)d0;        kz[1] = (unsigned)d1;
    } else {
        kx[0] = (unsigned)i0;               kx[1] = (unsigned)(i0 + 1);
        ky[0] = (unsigned)i1 * 2654435761u; ky[1] = (unsigned)(i1 + 1) * 2654435761u;
        kz[0] = (unsigned)i2 * 805459861u;  kz[1] = (unsigned)(i2 + 1) * 805459861u;
    }
    const unsigned mask = NENC - 1;

    __half2 acc = __float2half2_rn(0.0f);
    #pragma unroll
    for (int c = 0; c < 8; ++c) {
        const int ox = (c >> 2) & 1, oy = (c >> 1) & 1, oz = c & 1;
        unsigned id;
        if (DIRECT) id = kx[ox] + ky[oy] + kz[oz];
        else        id = (kx[ox] ^ ky[oy] ^ kz[oz]) & mask;
        const float   w  = wxy[2 * ox + oy] * wz[oz];
        const __half2 w2 = __float2half2_rn(w);
        acc = __hfma2(w2, tab[id], acc);
    }
    const float2 r = __half22float2(acc);
    return make_float2(r.x * INV_SCALE, r.y * INV_SCALE);
}

// ---------------------------------------------------------------- main
template <bool USE_TMA>
__global__ __launch_bounds__(TPB, 1)
void hashgrid_pair_kernel(const float* __restrict__ emb,
                          float4* __restrict__ out,
                          const __grid_constant__ CUtensorMap tmap)
{
    extern __shared__ char smem_raw[];
    float4*  stage = reinterpret_cast<float4*>(smem_raw);          // 2x16 KB
    __half2* tab   = reinterpret_cast<__half2*>(smem_raw + STAGE_BYTES);

    const int m     = blockIdx.x & (NPAIR - 1);
    const int chunk = blockIdx.x >> 3;
    const int lA = 2 * m, lB = 2 * m + 1;
    const int RA = c_res[lA], RB = c_res[lB];
    const int neA = c_nle[lA], neB = c_nle[lB];

    __half2* tabA = tab;
    __half2* tabB = tab + (neA + 1);

    const float2* __restrict__ srcA =
        reinterpret_cast<const float2*>(emb) + (size_t)lA * (NENC + 1);
    const float2* __restrict__ srcB =
        reinterpret_cast<const float2*>(emb) + (size_t)lB * (NENC + 1);
    for (int i = threadIdx.x; i <= neA; i += TPB) {
        const float2 v = srcA[i];
        tabA[i] = __floats2half2_rn(v.x * SCALE, v.y * SCALE);
    }
    for (int i = threadIdx.x; i <= neB; i += TPB) {
        const float2 v = srcB[i];
        tabB[i] = __floats2half2_rn(v.x * SCALE, v.y * SCALE);
    }
    __syncthreads();

    uint32_t stage_addr;
    if (USE_TMA) {
        asm("{ .reg .u64 t; cvta.to.shared.u64 t, %1; cvt.u32.u64 %0, t; }"
            : "=r"(stage_addr) : "l"(smem_raw));
    }

    #pragma unroll 1
    for (int g = 0; g < GPT; ++g) {
        const int pbase = chunk * PPB + g * TPB;
        const int p = pbase + threadIdx.x;

        if (USE_TMA && g >= 2) {
            // buffer g&1 was handed to TMA at iter g-2; wait for it
            if (threadIdx.x == 0)
                asm volatile("cp.async.bulk.wait_group 1;" ::: "memory");
            __syncthreads();
        }

        const float xv0 = g_xs[p];
        const float xv1 = g_xs[NPTS + p];
        const float xv2 = g_xs[2u * NPTS + p];

        float2 rA, rB;
        if (lA < 3) rA = level_feat<true >(tabA, RA, xv0, xv1, xv2);
        else        rA = level_feat<false>(tabA, RA, xv0, xv1, xv2);
        if (lB < 3) rB = level_feat<true >(tabB, RB, xv0, xv1, xv2);
        else        rB = level_feat<false>(tabB, RB, xv0, xv1, xv2);

        const float4 res = make_float4(rA.x, rA.y, rB.x, rB.y);

        if (USE_TMA) {
            float4* buf = stage + (g & 1) * TPB;
            buf[threadIdx.x] = res;
            __syncthreads();
            if (threadIdx.x == 0) {
                asm volatile("fence.proxy.async;" ::: "memory");
                const uint32_t ba = stage_addr + (g & 1) * (TPB * 16);
                #pragma unroll
                for (int j = 0; j < 4; ++j) {
                    asm volatile(
                        "cp.async.bulk.tensor.3d.global.shared::cta.tile.bulk_group "
                        "[%0, {%1, %2, %3}], [%4];"
                        :: "l"(&tmap), "r"(0), "r"(m), "r"(pbase + 256 * j),
                           "r"(ba + j * 4096)
                        : "memory");
                }
                asm volatile("cp.async.bulk.commit_group;" ::: "memory");
            }
        } else {
            out[(size_t)p * 8 + m] = res;
        }
    }
    if (USE_TMA && threadIdx.x == 0)
        asm volatile("cp.async.bulk.wait_group 0;" ::: "memory");
}

// ---------------------------------------------------------------- launch
typedef CUresult (*EncodeTiledFn)(
    CUtensorMap*, CUtensorMapDataType, cuuint32_t, void*,
    const cuuint64_t*, const cuuint64_t*, const cuuint32_t*, const cuuint32_t*,
    CUtensorMapInterleave, CUtensorMapSwizzle, CUtensorMapL2promotion,
    CUtensorMapFloatOOBfill);

extern "C" void kernel_launch(void* const* d_in, const int* in_sizes, int n_in,
                              void* d_out, int out_size)
{
    (void)n_in; (void)out_size;
    const float* x;
    const float* emb;
    if (in_sizes[0] == 3 * NPTS) { x = (const float*)d_in[0]; emb = (const float*)d_in[1]; }
    else                         { x = (const float*)d_in[1]; emb = (const float*)d_in[0]; }
    float4* out = (float4*)d_out;

    // Build tensormap for out viewed as f32 tensor [NPTS][8][4] via dlopen'd
    // driver API (no -lcuda link dependency).
    CUtensorMap tmap;
    bool have_tma = false;
    {
        void* h = dlopen("libcuda.so.1", RTLD_NOW | RTLD_GLOBAL);
        if (!h) h = dlopen("libcuda.so", RTLD_NOW | RTLD_GLOBAL);
        if (h) {
            EncodeTiledFn enc = (EncodeTiledFn)dlsym(h, "cuTensorMapEncodeTiled");
            if (enc) {
                cuuint64_t dims[3]    = {4, NPAIR, NPTS};
                cuuint64_t strides[2] = {16, 128};            // bytes
                cuuint32_t box[3]     = {4, 1, 256};
                cuuint32_t es[3]      = {1, 1, 1};
                CUresult r = enc(&tmap, CU_TENSOR_MAP_DATA_TYPE_FLOAT32, 3,
                                 (void*)d_out, dims, strides, box, es,
                                 CU_TENSOR_MAP_INTERLEAVE_NONE,
                                 CU_TENSOR_MAP_SWIZZLE_NONE,
                                 CU_TENSOR_MAP_L2_PROMOTION_L2_128B,
                                 CU_TENSOR_MAP_FLOAT_OOB_FILL_NONE);
                have_tma = (r == CUDA_SUCCESS);
            }
        }
    }
    if (!have_tma) { for (int i = 0; i < 16; ++i) ((cuuint64_t*)&tmap)[i] = 0; }

    cudaFuncSetAttribute(hashgrid_pair_kernel<true>,
                         cudaFuncAttributeMaxDynamicSharedMemorySize, SMEM_BYTES);
    cudaFuncSetAttribute(hashgrid_pair_kernel<false>,
                         cudaFuncAttributeMaxDynamicSharedMemorySize, SMEM_BYTES);

    transpose_x_kernel<<<NPTS / 1024, 1024>>>(x);

    const int blocks = (NPTS / PPB) * NPAIR;      // 1024
    if (have_tma)
        hashgrid_pair_kernel<true ><<<blocks, TPB, SMEM_BYTES>>>(emb, out, tmap);
    else
        hashgrid_pair_kernel<false><<<blocks, TPB, SMEM_BYTES>>>(emb, out, tmap);
}

// round 5
// speedup vs baseline: 1.1848x; 1.1848x over previous
#include <cuda_runtime.h>
#include <cuda_fp16.h>
#include <stdint.h>

// MultiLevelSparseHashEncoding — round 5.
// Round-4 TMA store FAILED (16B rows too slow, loop serialized on barriers).
// Keep the insight (scatter STG = 1/3 of L1 work), fix differently:
//  * main kernel stores half4 results COALESCED into stage[pair][point]
//    (2 wavefronts/warp instead of 32), storing raw scaled-fp16 acc bits.
//  * separate transpose kernel: stage -> out via padded SMEM exchange,
//    all phases coalesced / conflict-free, fp16->fp32 * 2^-12 on the fly.

#define NLVL 16
#define NENC 16384
#define NPTS (1 << 20)
#define TPB  1024
#define PPB  8192
#define GPT  (PPB / TPB)            // 8 points per thread
#define NPAIR 8
#define SMEM_BYTES ((2 * (NENC + 1)) * (int)sizeof(__half2))   // 131080
#define SCALE    4096.0f
#define INV_SCALE (1.0f / 4096.0f)

__constant__ int c_res[NLVL] = {16, 20, 25, 32, 40, 50, 64, 80,
                                101, 128, 161, 203, 256, 322, 406, 512};
__constant__ int c_nle[NLVL] = {4096, 8000, 15625, 16384, 16384, 16384,
                                16384, 16384, 16384, 16384, 16384, 16384,
                                16384, 16384, 16384, 16384};

__device__ float g_xs[3u * NPTS];          // SoA coords (12 MB)
__device__ uint2 g_stage[(size_t)NPAIR * NPTS];   // [pair][point] half4 (64 MB)

// ---------------------------------------------------------------- pre-kernel
__global__ __launch_bounds__(1024)
void transpose_x_kernel(const float* __restrict__ x)
{
    const int p = blockIdx.x * 1024 + threadIdx.x;
    const float a = x[3 * p + 0];
    const float b = x[3 * p + 1];
    const float c = x[3 * p + 2];
    g_xs[p]             = a;
    g_xs[NPTS + p]      = b;
    g_xs[2u * NPTS + p] = c;
}

// ---------------------------------------------------------------- per-level
// returns the fp16 accumulator still scaled by 2^12
template <bool DIRECT>
__device__ __forceinline__ __half2
level_feat(const __half2* __restrict__ tab, const int R,
           const float xv0, const float xv1, const float xv2)
{
    const float halfR = 0.5f * (float)R;
    const float t0 = __fadd_rn(__fmul_rn(__fadd_rn(xv0, 1.0f), halfR), -0.5f);
    const float t1 = __fadd_rn(__fmul_rn(__fadd_rn(xv1, 1.0f), halfR), -0.5f);
    const float t2 = __fadd_rn(__fmul_rn(__fadd_rn(xv2, 1.0f), halfR), -0.5f);

    const float fl0 = floorf(t0), fl1 = floorf(t1), fl2 = floorf(t2);
    const float fr0 = t0 - fl0, fr1 = t1 - fl1, fr2 = t2 - fl2;
    const int   i0  = (int)fl0, i1 = (int)fl1, i2 = (int)fl2;

    // validity folded into per-dim weights: invalid corner -> weight 0
    const float wx0 = i0     >= 0 ? 1.0f - fr0 : 0.0f;
    const float wx1 = i0 + 1 <  R ? fr0        : 0.0f;
    const float wy0 = i1     >= 0 ? 1.0f - fr1 : 0.0f;
    const float wy1 = i1 + 1 <  R ? fr1        : 0.0f;
    const float wz[2] = {i2     >= 0 ? 1.0f - fr2 : 0.0f,
                         i2 + 1 <  R ? fr2        : 0.0f};
    const float wxy[4] = {wx0 * wy0, wx0 * wy1, wx1 * wy0, wx1 * wy1};

    unsigned kx[2], ky[2], kz[2];
    if (DIRECT) {
        const int R2 = R * R;
        const int a0 = max(i0, 0), a1 = min(i0 + 1, R - 1);
        const int b0 = max(i1, 0), b1 = min(i1 + 1, R - 1);
        const int d0 = max(i2, 0), d1 = min(i2 + 1, R - 1);
        kx[0] = (unsigned)(a0 * R2); kx[1] = (unsigned)(a1 * R2);
        ky[0] = (unsigned)(b0 * R);  ky[1] = (unsigned)(b1 * R);
        kz[0] = (unsigned)d0;        kz[1] = (unsigned)d1;
    } else {
        kx[0] = (unsigned)i0;               kx[1] = (unsigned)(i0 + 1);
        ky[0] = (unsigned)i1 * 2654435761u; ky[1] = (unsigned)(i1 + 1) * 2654435761u;
        kz[0] = (unsigned)i2 * 805459861u;  kz[1] = (unsigned)(i2 + 1) * 805459861u;
    }
    const unsigned mask = NENC - 1;

    __half2 acc = __float2half2_rn(0.0f);
    #pragma unroll
    for (int c = 0; c < 8; ++c) {
        const int ox = (c >> 2) & 1, oy = (c >> 1) & 1, oz = c & 1;
        unsigned id;
        if (DIRECT) id = kx[ox] + ky[oy] + kz[oz];
        else        id = (kx[ox] ^ ky[oy] ^ kz[oz]) & mask;
        const float   w  = wxy[2 * ox + oy] * wz[oz];
        const __half2 w2 = __float2half2_rn(w);
        acc = __hfma2(w2, tab[id], acc);
    }
    return acc;
}

// ---------------------------------------------------------------- main
__global__ __launch_bounds__(TPB, 1)
void hashgrid_pair_kernel(const float* __restrict__ emb)
{
    extern __shared__ __half2 tab[];

    const int m     = blockIdx.x & (NPAIR - 1);   // pair index (fastest)
    const int chunk = blockIdx.x >> 3;
    const int lA = 2 * m, lB = 2 * m + 1;
    const int RA = c_res[lA], RB = c_res[lB];
    const int neA = c_nle[lA], neB = c_nle[lB];

    __half2* tabA = tab;
    __half2* tabB = tab + (neA + 1);

    const float2* __restrict__ srcA =
        reinterpret_cast<const float2*>(emb) + (size_t)lA * (NENC + 1);
    const float2* __restrict__ srcB =
        reinterpret_cast<const float2*>(emb) + (size_t)lB * (NENC + 1);
    for (int i = threadIdx.x; i <= neA; i += TPB) {
        const float2 v = srcA[i];
        tabA[i] = __floats2half2_rn(v.x * SCALE, v.y * SCALE);
    }
    for (int i = threadIdx.x; i <= neB; i += TPB) {
        const float2 v = srcB[i];
        tabB[i] = __floats2half2_rn(v.x * SCALE, v.y * SCALE);
    }
    __syncthreads();

    uint2* __restrict__ stage = g_stage + (size_t)m * NPTS;

    int p = chunk * PPB + threadIdx.x;
    #pragma unroll 1
    for (int g = 0; g < GPT; ++g, p += TPB) {
        const float xv0 = g_xs[p];
        const float xv1 = g_xs[NPTS + p];
        const float xv2 = g_xs[2u * NPTS + p];

        __half2 rA, rB;
        if (lA < 3) rA = level_feat<true >(tabA, RA, xv0, xv1, xv2);
        else        rA = level_feat<false>(tabA, RA, xv0, xv1, xv2);
        if (lB < 3) rB = level_feat<true >(tabB, RB, xv0, xv1, xv2);
        else        rB = level_feat<false>(tabB, RB, xv0, xv1, xv2);

        // coalesced 8 B store of the raw scaled-fp16 bits
        stage[p] = make_uint2(*reinterpret_cast<unsigned*>(&rA),
                              *reinterpret_cast<unsigned*>(&rB));
    }
}

// ---------------------------------------------------------------- transpose
#define TPB3 256
__global__ __launch_bounds__(TPB3)
void transpose_out_kernel(float4* __restrict__ out)
{
    __shared__ uint2 arr[NPAIR][TPB3 + 1];        // pitch 257 -> conflict-free

    const int base = blockIdx.x * TPB3;
    const int tid  = threadIdx.x;

    #pragma unroll
    for (int m = 0; m < NPAIR; ++m)
        arr[m][tid] = g_stage[(size_t)m * NPTS + base + tid];
    __syncthreads();

    // out float4 index range [base*8, base*8 + 2048), fully coalesced
    #pragma unroll
    for (int k = 0; k < 8; ++k) {
        const int local = tid + TPB3 * k;         // p_off*8 + m
        const int p_off = local >> 3;
        const int m     = local & 7;
        const uint2 v = arr[m][p_off];
        const __half2 ha = *reinterpret_cast<const __half2*>(&v.x);
        const __half2 hb = *reinterpret_cast<const __half2*>(&v.y);
        const float2 fa = __half22float2(ha);
        const float2 fb = __half22float2(hb);
        out[(size_t)base * 8 + local] =
            make_float4(fa.x * INV_SCALE, fa.y * INV_SCALE,
                        fb.x * INV_SCALE, fb.y * INV_SCALE);
    }
}

// ---------------------------------------------------------------- launch
extern "C" void kernel_launch(void* const* d_in, const int* in_sizes, int n_in,
                              void* d_out, int out_size)
{
    (void)n_in; (void)out_size;
    const float* x;
    const float* emb;
    if (in_sizes[0] == 3 * NPTS) { x = (const float*)d_in[0]; emb = (const float*)d_in[1]; }
    else                         { x = (const float*)d_in[1]; emb = (const float*)d_in[0]; }
    float4* out = (float4*)d_out;

    cudaFuncSetAttribute(hashgrid_pair_kernel,
                         cudaFuncAttributeMaxDynamicSharedMemorySize, SMEM_BYTES);

    transpose_x_kernel<<<NPTS / 1024, 1024>>>(x);

    const int blocks = (NPTS / PPB) * NPAIR;      // 1024
    hashgrid_pair_kernel<<<blocks, TPB, SMEM_BYTES>>>(emb);

    transpose_out_kernel<<<NPTS / TPB3, TPB3>>>(out);
}